// round 8
// baseline (speedup 1.0000x reference)
#include <cuda_runtime.h>
#include <cuda_bf16.h>
#include <stdint.h>
#include <math.h>

// out[i] = center[argmin_m |x[i] - center[m]|]  (exact jnp.argmin, first-min
// wins). Forward value of the straight-through soft quantizer.
//
// 2048-cell interval table over an affine-mapped domain. Pure cells store the
// winning center VALUE (4B). Boundary cells store a NaN whose mantissa packs
// the two candidate indices -> exact 2-way fp32 compare. Tag 0x200 -> exact
// 16-way scan (pathological spacing / degenerate centers).

#define NC      16
#define NCELLS  2048

__device__ float  g_cells[NCELLS];
__device__ float2 g_affine;  // {S, B}: u = fma(x, S, B) maps boundary span to [1,2)

// ---------------------------------------------------------------- prep ----
__global__ void prep_kernel(const float* __restrict__ center) {
    __shared__ float  s_val[NC];
    __shared__ int    s_orig[NC];
    __shared__ double s_thr[NC - 1];
    __shared__ float  s_SB[2];

    int t = threadIdx.x;

    // Stable rank sort (equal values keep original order).
    if (t < NC) {
        float ct = center[t];
        int rank = 0;
        for (int j = 0; j < NC; ++j) {
            float cj = center[j];
            if (cj < ct || (cj == ct && j < t)) rank++;
        }
        s_val[rank]  = ct;
        s_orig[rank] = t;
    }
    __syncthreads();

    if (t == 0) {
        for (int r = 0; r < NC - 1; ++r)
            s_thr[r] = 0.5 * ((double)s_val[r] + (double)s_val[r + 1]);
        double lo = s_thr[0], hi = s_thr[NC - 2];
        float S, B;
        if (hi - lo > 1e-30) {
            S = (float)(1.0 / (hi - lo));
            B = (float)(1.0 - lo * (double)S);
        } else {           // degenerate spacing: everything -> full-scan tag
            S = 0.0f; B = 1.5f;
        }
        s_SB[0] = S; s_SB[1] = B;
        g_affine = make_float2(S, B);
    }
    __syncthreads();

    double S = (double)s_SB[0], B = (double)s_SB[1];
    double invS = (S != 0.0) ? (1.0 / S) : 0.0;   // one DP divide per thread
    const double slack = 4e-6;  // u-units; cell width 4.88e-4; fp32 fma err ~1e-7

    for (int j = t; j < NCELLS; j += blockDim.x) {
        double xlo, xhi;
        if (S == 0.0) { xlo = -INFINITY; xhi = INFINITY; }
        else {
            xlo = (j == 0) ? -INFINITY
                 : ((1.0 + (double)j / NCELLS - slack) - B) * invS;
            xhi = (j == NCELLS - 1) ? INFINITY
                 : ((1.0 + (double)(j + 1) / NCELLS + slack) - B) * invS;
        }
        int klo = 0, nb = 0;
        for (int r = 0; r < NC - 1; ++r) {
            double th = s_thr[r];
            if (th <= xlo) klo++;
            else if (th < xhi) nb++;
        }
        float cell;
        if (nb == 0) {
            cell = s_val[klo];                       // pure cell: value direct
        } else if (nb == 1) {
            // NaN payload: bit8 tag + (p<<4)|q, p = tie-winner = lower ORIGINAL
            // index (jnp.argmin first-wins). Store ORIGINAL indices.
            int a = s_orig[klo], b = s_orig[klo + 1];
            int p = (a < b) ? a : b;
            int q = (a < b) ? b : a;
            cell = __int_as_float(0x7FC00000 | 0x100 | (p << 4) | q);
        } else {
            cell = __int_as_float(0x7FC00000 | 0x200);  // full-scan tag
        }
        g_cells[j] = cell;
    }
}

// ---------------------------------------------------------------- main ----
__device__ __forceinline__ float quant1(float x, float S, float B,
                                        const float* __restrict__ cells,
                                        const float* __restrict__ co) {
    float u = fmaf(x, S, B);
    u = fminf(fmaxf(u, 1.0f), __uint_as_float(0x3FFFFFFFu));  // clamp [1,2)
    unsigned j = (__float_as_uint(u) >> 12) & 0x7FFu;         // floor((u-1)*2048)
    float r = cells[j];
    if (__builtin_expect(r != r, 0)) {   // NaN sentinel: rare slow path
        unsigned m = __float_as_uint(r);
        if (m & 0x100u) {
            // 2-candidate boundary cell: exact fp32 compare, tie -> p.
            float cp = co[(m >> 4) & 0xFu];
            float cq = co[m & 0xFu];
            r = (fabsf(x - cq) < fabsf(x - cp)) ? cq : cp;
        } else {
            // exact 16-way scan, original order, first-min wins
            float bd = fabsf(x - co[0]);
            r = co[0];
#pragma unroll
            for (int k = 1; k < NC; ++k) {
                float d = fabsf(x - co[k]);
                if (d < bd) { bd = d; r = co[k]; }
            }
        }
    }
    return r;
}

__device__ __forceinline__ float4 quant4(float4 v, float S, float B,
                                         const float* __restrict__ cells,
                                         const float* __restrict__ co) {
    float4 r;
    r.x = quant1(v.x, S, B, cells, co);
    r.y = quant1(v.y, S, B, cells, co);
    r.z = quant1(v.z, S, B, cells, co);
    r.w = quant1(v.w, S, B, cells, co);
    return r;
}

__global__ void __launch_bounds__(256) main_kernel(
    const float4* __restrict__ x4, float4* __restrict__ out4, int n4,
    const float* __restrict__ x, float* __restrict__ out,
    int tail_start, int n, const float* __restrict__ center)
{
    __shared__ float s_cells[NCELLS];   // 8 KB
    __shared__ float s_co[NC];

    {
        const float4* __restrict__ gsrc = (const float4*)g_cells;
        float4* __restrict__ sdst = (float4*)s_cells;
#pragma unroll
        for (int i = threadIdx.x; i < NCELLS / 4; i += 256) sdst[i] = gsrc[i];
        if (threadIdx.x < NC) s_co[threadIdx.x] = center[threadIdx.x];
    }
    __syncthreads();

    float2 SB = g_affine;
    float S = SB.x, Bc = SB.y;

    int stride = gridDim.x * blockDim.x;
    int i0 = blockIdx.x * blockDim.x + threadIdx.x;

    // 2x unrolled grid-stride: both loads in flight before either lookup.
    int i = i0;
    for (; i + stride < n4; i += 2 * stride) {
        float4 a = x4[i];
        float4 b = x4[i + stride];
        float4 ra = quant4(a, S, Bc, s_cells, s_co);
        float4 rb = quant4(b, S, Bc, s_cells, s_co);
        out4[i] = ra;
        out4[i + stride] = rb;
    }
    for (; i < n4; i += stride) {
        out4[i] = quant4(x4[i], S, Bc, s_cells, s_co);
    }
    for (int k = tail_start + i0; k < n; k += stride) {
        out[k] = quant1(x[k], S, Bc, s_cells, s_co);
    }
}

// -------------------------------------------------------------- launch ----
extern "C" void kernel_launch(void* const* d_in, const int* in_sizes, int n_in,
                              void* d_out, int out_size) {
    const float* xp     = (const float*)d_in[0];
    const float* center = (const float*)d_in[1];
    float* outp         = (float*)d_out;

    int n = in_sizes[0];

    prep_kernel<<<1, 256>>>(center);

    bool aligned = ((((uintptr_t)xp) | ((uintptr_t)outp)) & 0xF) == 0;
    int n4 = aligned ? (n >> 2) : 0;
    int tail_start = n4 << 2;

    int blocks = 148 * 8;   // grid-stride loop; wave shape absorbed by striding
    main_kernel<<<blocks, 256>>>((const float4*)xp, (float4*)outp, n4,
                                 xp, outp, tail_start, n, center);
}

// round 9
// speedup vs baseline: 1.3243x; 1.3243x over previous
#include <cuda_runtime.h>
#include <cuda_bf16.h>
#include <stdint.h>
#include <math.h>

// out[i] = center[argmin_m |x[i] - center[m]|]  (exact jnp.argmin, first-min
// wins). Forward value of the straight-through soft quantizer.
//
// 15 Voronoi boundaries -> 2048-cell interval table; each cell stores its <=2
// candidate centers, tie-ordered. Hot path is branchless: FFMA + bit-trick
// index, one LDS.64, one exact 2-way fp32 distance compare.

#define NC      16
#define NCELLS  2048

__device__ float2 g_cells[NCELLS];
__device__ float2 g_affine;  // {S, B}: u = fma(x, S, B) maps boundary span to [1,2)

// ---------------------------------------------------------------- prep ----
// Parallel across blocks: every block redundantly computes the (deterministic)
// sorted centers / thresholds / affine map, then fills a grid-stride slice of
// the cell table. All blocks write identical g_affine values (benign).
__global__ void prep_kernel(const float* __restrict__ center) {
    __shared__ float  s_val[NC];
    __shared__ int    s_orig[NC];
    __shared__ double s_thr[NC - 1];
    __shared__ float  s_SB[2];

    int t = threadIdx.x;

    // Stable rank sort (equal values keep original order).
    if (t < NC) {
        float ct = center[t];
        int rank = 0;
        for (int j = 0; j < NC; ++j) {
            float cj = center[j];
            if (cj < ct || (cj == ct && j < t)) rank++;
        }
        s_val[rank]  = ct;
        s_orig[rank] = t;
    }
    __syncthreads();

    if (t == 0) {
        for (int r = 0; r < NC - 1; ++r)
            s_thr[r] = 0.5 * ((double)s_val[r] + (double)s_val[r + 1]);
        double lo = s_thr[0], hi = s_thr[NC - 2];
        float S, B;
        if (hi - lo > 1e-30) {
            S = (float)(1.0 / (hi - lo));
            B = (float)(1.0 - lo * (double)S);
        } else {           // degenerate spacing: everything -> sentinel path
            S = 0.0f; B = 1.5f;
        }
        s_SB[0] = S; s_SB[1] = B;
        g_affine = make_float2(S, B);
    }
    __syncthreads();

    double S = (double)s_SB[0], B = (double)s_SB[1];
    double invS = (S != 0.0) ? (1.0 / S) : 0.0;   // one DP divide per thread
    const double slack = 4e-6;  // u-units; cell width 4.88e-4; fp32 fma err ~1e-7

    int j0 = blockIdx.x * blockDim.x + t;
    int jstride = gridDim.x * blockDim.x;
    for (int j = j0; j < NCELLS; j += jstride) {
        double xlo, xhi;
        if (S == 0.0) { xlo = -INFINITY; xhi = INFINITY; }
        else {
            xlo = (j == 0) ? -INFINITY
                 : ((1.0 + (double)j / NCELLS - slack) - B) * invS;
            xhi = (j == NCELLS - 1) ? INFINITY
                 : ((1.0 + (double)(j + 1) / NCELLS + slack) - B) * invS;
        }
        int klo = 0, nb = 0;
        for (int r = 0; r < NC - 1; ++r) {
            double th = s_thr[r];
            if (th <= xlo) klo++;
            else if (th < xhi) nb++;
        }
        float2 pq;
        if (nb == 0) {
            pq.x = s_val[klo]; pq.y = s_val[klo];
        } else if (nb == 1) {
            // p (stored first) wins exact fp32 ties -> must be lower ORIGINAL
            // index (jnp.argmin first-wins).
            float a = s_val[klo], b = s_val[klo + 1];
            if (s_orig[klo] < s_orig[klo + 1]) { pq.x = a; pq.y = b; }
            else                               { pq.x = b; pq.y = a; }
        } else {
            pq.x = __int_as_float(0x7FC00000);  // NaN sentinel -> exact scan
            pq.y = pq.x;
        }
        g_cells[j] = pq;
    }
}

// ---------------------------------------------------------------- main ----
__device__ __forceinline__ float quant1(float x, float S, float B,
                                        const float2* __restrict__ cells,
                                        const float* __restrict__ co) {
    float u = fmaf(x, S, B);
    u = fminf(fmaxf(u, 1.0f), __uint_as_float(0x3FFFFFFFu));  // clamp [1,2)
    unsigned j = (__float_as_uint(u) >> 12) & 0x7FFu;         // floor((u-1)*2048)
    float2 pq = cells[j];
    float dP = x - pq.x;
    float dQ = x - pq.y;
    float r = (fabsf(dQ) < fabsf(dP)) ? pq.y : pq.x;          // tie -> p
    if (r != r) {  // NaN sentinel (pathological table cell): exact 16-way scan
        float bd = fabsf(x - co[0]);
        r = co[0];
#pragma unroll
        for (int m = 1; m < NC; ++m) {
            float d = fabsf(x - co[m]);
            if (d < bd) { bd = d; r = co[m]; }
        }
    }
    return r;
}

__device__ __forceinline__ float4 quant4(float4 v, float S, float B,
                                         const float2* __restrict__ cells,
                                         const float* __restrict__ co) {
    float4 r;
    r.x = quant1(v.x, S, B, cells, co);
    r.y = quant1(v.y, S, B, cells, co);
    r.z = quant1(v.z, S, B, cells, co);
    r.w = quant1(v.w, S, B, cells, co);
    return r;
}

__global__ void __launch_bounds__(256) main_kernel(
    const float4* __restrict__ x4, float4* __restrict__ out4, int n4,
    const float* __restrict__ x, float* __restrict__ out,
    int tail_start, int n, const float* __restrict__ center)
{
    __shared__ float2 s_cells[NCELLS];   // 16 KB
    __shared__ float  s_co[NC];

    {
        const float4* __restrict__ gsrc = (const float4*)g_cells;
        float4* __restrict__ sdst = (float4*)s_cells;
#pragma unroll
        for (int i = threadIdx.x; i < NCELLS / 2; i += 256) sdst[i] = gsrc[i];
        if (threadIdx.x < NC) s_co[threadIdx.x] = center[threadIdx.x];
    }
    __syncthreads();

    float2 SB = g_affine;
    float S = SB.x, Bc = SB.y;

    int stride = gridDim.x * blockDim.x;
    int i0 = blockIdx.x * blockDim.x + threadIdx.x;

    // 2x unrolled grid-stride: both loads in flight before either lookup.
    int i = i0;
    for (; i + stride < n4; i += 2 * stride) {
        float4 a = x4[i];
        float4 b = x4[i + stride];
        float4 ra = quant4(a, S, Bc, s_cells, s_co);
        float4 rb = quant4(b, S, Bc, s_cells, s_co);
        out4[i] = ra;
        out4[i + stride] = rb;
    }
    for (; i < n4; i += stride) {
        out4[i] = quant4(x4[i], S, Bc, s_cells, s_co);
    }
    for (int k = tail_start + i0; k < n; k += stride) {
        out[k] = quant1(x[k], S, Bc, s_cells, s_co);
    }
}

// -------------------------------------------------------------- launch ----
extern "C" void kernel_launch(void* const* d_in, const int* in_sizes, int n_in,
                              void* d_out, int out_size) {
    const float* xp     = (const float*)d_in[0];
    const float* center = (const float*)d_in[1];
    float* outp         = (float*)d_out;

    int n = in_sizes[0];

    prep_kernel<<<32, 256>>>(center);   // ~1 us: cells split across 32 blocks

    bool aligned = ((((uintptr_t)xp) | ((uintptr_t)outp)) & 0xF) == 0;
    int n4 = aligned ? (n >> 2) : 0;
    int tail_start = n4 << 2;

    // regs=40 -> 6 blocks/SM (register-limited); 148 SMs x 6 = one exact wave.
    int blocks = 148 * 6;
    main_kernel<<<blocks, 256>>>((const float4*)xp, (float4*)outp, n4,
                                 xp, outp, tail_start, n, center);
}